// round 2
// baseline (speedup 1.0000x reference)
#include <cuda_runtime.h>
#include <math.h>

// ---------------- problem constants ----------------
#define NRBF     32
#define CUTOFF_F 5.0f
#define GAMMA_F  40.96f                 // (NRBF/CUTOFF)^2 = (32/5)^2
#define STEP_F   (5.0f / 31.0f)         // linspace(0,5,32) spacing
#define INVSTEP_F (31.0f / 5.0f)
#define PI_F     3.14159265358979323846f
#define MAXN     50000

// scratch accumulator [N,16,8] (allowed: __device__ global, no runtime alloc)
__device__ float g_agg[(size_t)MAXN * 128];

// ---------------- zero the accumulator ----------------
__global__ void zero_kernel(int n4) {
    int i = blockIdx.x * blockDim.x + threadIdx.x;
    float4* p = (float4*)g_agg;
    if (i < n4) p[i] = make_float4(0.f, 0.f, 0.f, 0.f);
}

// ---------------- edge pass ----------------
// 16 threads per edge; thread = one channel c. 256 threads/block = 16 edges.
__global__ void __launch_bounds__(256) edge_kernel(
    const float* __restrict__ h,
    const float* __restrict__ pos,
    const int*   __restrict__ ei,
    const float* __restrict__ Wrbf,   // [32,16] row-major
    int E)
{
    __shared__ float sW[NRBF * 16];
    int t = threadIdx.x;
    sW[t]       = Wrbf[t];
    sW[t + 256] = Wrbf[t + 256];
    __syncthreads();

    int e = blockIdx.x * 16 + (t >> 4);
    if (e >= E) return;
    int lane = t & 15;

    int src = ei[e];
    int dst = ei[E + e];

    float rx = pos[dst * 3 + 0] - pos[src * 3 + 0];
    float ry = pos[dst * 3 + 1] - pos[src * 3 + 1];
    float rz = pos[dst * 3 + 2] - pos[src * 3 + 2];
    float d  = sqrtf(rx * rx + ry * ry + rz * rz + 1e-12f);
    if (d >= CUTOFF_F) return;          // env == 0 -> message is exactly zero

    float inv = 1.0f / d;
    float ux = rx * inv, uy = ry * inv, uz = rz * inv;

    // ----- radial weight: truncated gaussian smearing (9 terms around d) -----
    int k0 = __float2int_rn(d * INVSTEP_F);
    k0 = min(max(k0, 0), 31);

    float r = 0.f;
    {
        int k = k0 + lane - 4;
        if (lane < 9 && k >= 0 && k <= 31) {
            float dd = d - (float)k * STEP_F;
            r = __expf(-GAMMA_F * dd * dd);
        }
    }

    // group-local shuffle mask (16-lane group inside the warp; groups diverge together)
    unsigned base = (unsigned)(t & 16);
    unsigned mask = 0xFFFFu << base;

    float w = 0.f;
    #pragma unroll
    for (int m = 0; m < 9; m++) {
        float rm = __shfl_sync(mask, r, base + m, 32);
        int km = k0 + m - 4;
        int kc = min(max(km, 0), 31);   // rm==0 when out of range; clamp only for address safety
        w += rm * sW[kc * 16 + lane];
    }
    float env = 0.5f * (__cosf((PI_F / CUTOFF_F) * d) + 1.0f);
    w *= env;

    // ----- gather h[src] channel c=lane, geometric product with unit vector -----
    const float4* hp = (const float4*)(h + (size_t)src * 128 + lane * 8);
    float4 A0 = hp[0], A1 = hp[1];
    float a0 = A0.x, a1 = A0.y, a2 = A0.z, a3 = A0.w;
    float a4 = A1.x, a5 = A1.y, a6 = A1.z, a7 = A1.w;

    // gp(a, u) with u = ux e1 + uy e2 + uz e3, Cl(3,0) shortlex basis
    float m0 = (a1 * ux + a2 * uy + a3 * uz) * w;
    float m1 = (a0 * ux + a4 * uy + a5 * uz) * w;
    float m2 = (a0 * uy + a6 * uz - a4 * ux) * w;
    float m3 = (a0 * uz - a5 * ux - a6 * uy) * w;
    float m4 = (a1 * uy + a7 * uz - a2 * ux) * w;
    float m5 = (a1 * uz - a3 * ux - a7 * uy) * w;
    float m6 = (a7 * ux - a3 * uy + a2 * uz) * w;
    float m7 = (a6 * ux - a5 * uy + a4 * uz) * w;

    float* p = g_agg + (size_t)dst * 128 + lane * 8;
    asm volatile("red.global.add.v4.f32 [%0], {%1,%2,%3,%4};"
                 :: "l"(p), "f"(m0), "f"(m1), "f"(m2), "f"(m3) : "memory");
    asm volatile("red.global.add.v4.f32 [%0], {%1,%2,%3,%4};"
                 :: "l"(p + 4), "f"(m4), "f"(m5), "f"(m6), "f"(m7) : "memory");
}

// ---------------- node pass ----------------
// 128 threads/block = 8 nodes; thread = (node_local, out-channel o).
__global__ void __launch_bounds__(128) node_kernel(
    const float* __restrict__ h,
    const float* __restrict__ Wout,   // [16,16] row-major: W[c*16+o]
    const float* __restrict__ Wsgp,
    float* __restrict__ res,
    int N)
{
    __shared__ float s_a[1024];   // agg tile   [8][16][8]
    __shared__ float s_h[1024];   // h tile
    __shared__ float s_wo[256];
    __shared__ float s_wq[256];

    int t = threadIdx.x;
    s_wo[t] = Wout[t];       s_wo[t + 128] = Wout[t + 128];
    s_wq[t] = Wsgp[t];       s_wq[t + 128] = Wsgp[t + 128];

    int basen = blockIdx.x * 8;
    int nvalid = min(8, N - basen);
    int f4count = nvalid * 32;                  // float4s in tile

    const float4* ga = (const float4*)(g_agg + (size_t)basen * 128);
    const float4* gh = (const float4*)(h     + (size_t)basen * 128);
    float4* sa = (float4*)s_a;
    float4* sh = (float4*)s_h;
    if (t < f4count)        { sa[t]       = ga[t];       sh[t]       = gh[t]; }
    if (t + 128 < f4count)  { sa[t + 128] = ga[t + 128]; sh[t + 128] = gh[t + 128]; }
    __syncthreads();

    int nl = t >> 4;
    if (basen + nl >= N) return;
    int o = t & 15;

    float a[8], q[8];
    #pragma unroll
    for (int i = 0; i < 8; i++) { a[i] = 0.f; q[i] = 0.f; }

    const float4* A4 = (const float4*)(s_a + nl * 128);
    const float4* H4 = (const float4*)(s_h + nl * 128);

    #pragma unroll
    for (int c = 0; c < 16; c++) {
        float wo = s_wo[c * 16 + o];
        float wq = s_wq[c * 16 + o];
        float4 x0 = A4[c * 2], x1 = A4[c * 2 + 1];
        float4 y0 = H4[c * 2], y1 = H4[c * 2 + 1];
        a[0] += x0.x * wo; a[1] += x0.y * wo; a[2] += x0.z * wo; a[3] += x0.w * wo;
        a[4] += x1.x * wo; a[5] += x1.y * wo; a[6] += x1.z * wo; a[7] += x1.w * wo;
        q[0] += y0.x * wq; q[1] += y0.y * wq; q[2] += y0.z * wq; q[3] += y0.w * wq;
        q[4] += y1.x * wq; q[5] += y1.y * wq; q[6] += y1.z * wq; q[7] += y1.w * wq;
    }

    // full Cl(3,0) geometric product g = gp(a, q)
    float g0 = a[0]*q[0] + a[1]*q[1] + a[2]*q[2] + a[3]*q[3] - a[4]*q[4] - a[5]*q[5] - a[6]*q[6] - a[7]*q[7];
    float g1 = a[0]*q[1] + a[1]*q[0] - a[2]*q[4] - a[3]*q[5] + a[4]*q[2] + a[5]*q[3] - a[6]*q[7] - a[7]*q[6];
    float g2 = a[0]*q[2] + a[1]*q[4] + a[2]*q[0] - a[3]*q[6] - a[4]*q[1] + a[5]*q[7] + a[6]*q[3] + a[7]*q[5];
    float g3 = a[0]*q[3] + a[1]*q[5] + a[2]*q[6] + a[3]*q[0] - a[4]*q[7] - a[5]*q[1] - a[6]*q[2] - a[7]*q[4];
    float g4 = a[0]*q[4] + a[1]*q[2] - a[2]*q[1] + a[3]*q[7] + a[4]*q[0] - a[5]*q[6] + a[6]*q[5] + a[7]*q[3];
    float g5 = a[0]*q[5] + a[1]*q[3] - a[2]*q[7] - a[3]*q[1] + a[4]*q[6] + a[5]*q[0] - a[6]*q[4] - a[7]*q[2];
    float g6 = a[0]*q[6] + a[1]*q[7] + a[2]*q[3] - a[3]*q[2] - a[4]*q[5] + a[5]*q[4] + a[6]*q[0] + a[7]*q[1];
    float g7 = a[0]*q[7] + a[1]*q[6] - a[2]*q[5] + a[3]*q[4] + a[4]*q[3] - a[5]*q[2] + a[6]*q[1] + a[7]*q[0];

    float* op = res + (size_t)(basen + nl) * 128 + o * 8;
    float4 r0 = make_float4(a[0] + g0, a[1] + g1, a[2] + g2, a[3] + g3);
    float4 r1 = make_float4(a[4] + g4, a[5] + g5, a[6] + g6, a[7] + g7);
    ((float4*)op)[0] = r0;
    ((float4*)op)[1] = r1;
}

// ---------------- launch ----------------
extern "C" void kernel_launch(void* const* d_in, const int* in_sizes, int n_in,
                              void* d_out, int out_size)
{
    const float* h    = (const float*)d_in[0];   // [N,16,8]
    const float* pos  = (const float*)d_in[1];   // [N,3]
    const int*   ei   = (const int*)  d_in[2];   // [2,E]
    const float* Wrbf = (const float*)d_in[3];   // [32,16]
    const float* Wout = (const float*)d_in[4];   // [16,16]
    const float* Wsgp = (const float*)d_in[5];   // [16,16]
    float* out = (float*)d_out;

    int N = in_sizes[0] / 128;
    int E = in_sizes[2] / 2;
    if (N > MAXN) N = MAXN;

    int n4 = N * 32;
    zero_kernel<<<(n4 + 255) / 256, 256>>>(n4);
    edge_kernel<<<(E + 15) / 16, 256>>>(h, pos, ei, Wrbf, E);
    node_kernel<<<(N + 7) / 8, 128>>>(h, Wout, Wsgp, out, N);
}

// round 4
// speedup vs baseline: 1.1073x; 1.1073x over previous
#include <cuda_runtime.h>
#include <math.h>

// ---------------- problem constants ----------------
#define NRBF     32
#define CUTOFF_F 5.0f
#define GAMMA_F  40.96f                 // (NRBF/CUTOFF)^2
#define STEP_F   (5.0f / 31.0f)
#define INVSTEP_F (31.0f / 5.0f)
#define PI_F     3.14159265358979323846f
#define MAXN     50000
#define MAXE     800000

// scratch (static __device__ globals: allowed, no runtime alloc)
__device__ float  g_agg[(size_t)MAXN * 128];   // [N,16,8]
__device__ int    g_cnt;                       // survivor count
__device__ int2   g_sd[MAXE];                  // packed (src,dst)
__device__ float4 g_uvd[MAXE];                 // packed (ux,uy,uz,d)

// ---------------- filter + compact ----------------
__global__ void __launch_bounds__(256) filter_kernel(
    const float* __restrict__ pos,
    const int*   __restrict__ ei,
    int E)
{
    int e = blockIdx.x * blockDim.x + threadIdx.x;
    bool live = false;
    int src = 0, dst = 0;
    float ux = 0.f, uy = 0.f, uz = 0.f, d = 0.f;
    if (e < E) {
        src = ei[e];
        dst = ei[E + e];
        float rx = pos[dst * 3 + 0] - pos[src * 3 + 0];
        float ry = pos[dst * 3 + 1] - pos[src * 3 + 1];
        float rz = pos[dst * 3 + 2] - pos[src * 3 + 2];
        d = sqrtf(rx * rx + ry * ry + rz * rz + 1e-12f);
        if (d < CUTOFF_F) {
            live = true;
            float inv = 1.0f / d;
            ux = rx * inv; uy = ry * inv; uz = rz * inv;
        }
    }
    unsigned m = __ballot_sync(0xFFFFFFFFu, live);
    if (!m) return;
    int lane = threadIdx.x & 31;
    int leader = __ffs(m) - 1;
    int base = 0;
    if (lane == leader) base = atomicAdd(&g_cnt, __popc(m));
    base = __shfl_sync(0xFFFFFFFFu, base, leader);
    if (live) {
        int off = base + __popc(m & ((1u << lane) - 1u));
        g_sd[off]  = make_int2(src, dst);
        g_uvd[off] = make_float4(ux, uy, uz, d);
    }
}

// ---------------- heavy edge pass over survivors ----------------
// 16 threads per survivor (thread = channel); 256 threads/block = 16 survivors
// per iteration; grid-stride over the compacted list.
__global__ void __launch_bounds__(256) edge_kernel(
    const float* __restrict__ h,
    const float* __restrict__ Wrbf)   // [32,16] row-major
{
    __shared__ float sW[NRBF * 16];
    int t = threadIdx.x;
    sW[t]       = Wrbf[t];
    sW[t + 256] = Wrbf[t + 256];
    __syncthreads();

    int cnt = g_cnt;
    int lane = t & 15;
    unsigned gbase = (unsigned)(t & 16);
    unsigned gmask = 0xFFFFu << gbase;

    for (int i0 = blockIdx.x * 16 + (t >> 4); i0 < cnt; i0 += gridDim.x * 16) {
        int2   sd  = g_sd[i0];
        float4 uvd = g_uvd[i0];
        float ux = uvd.x, uy = uvd.y, uz = uvd.z, d = uvd.w;

        // prefetch the gather early so it overlaps the RBF math
        const float4* hp = (const float4*)(h + (size_t)sd.x * 128 + lane * 8);
        float4 A0 = hp[0], A1 = hp[1];

        // truncated gaussian smearing: 9 terms around d, cooperative exp
        int k0 = __float2int_rn(d * INVSTEP_F);
        k0 = min(max(k0, 0), 31);
        float r = 0.f;
        {
            int k = k0 + lane - 4;
            if (lane < 9 && k >= 0 && k <= 31) {
                float dd = d - (float)k * STEP_F;
                r = __expf(-GAMMA_F * dd * dd);
            }
        }
        float w = 0.f;
        #pragma unroll
        for (int m = 0; m < 9; m++) {
            float rm = __shfl_sync(gmask, r, gbase + m, 32);
            int km = k0 + m - 4;
            int kc = min(max(km, 0), 31);
            w += rm * sW[kc * 16 + lane];
        }
        w *= 0.5f * (__cosf((PI_F / CUTOFF_F) * d) + 1.0f);

        float a0 = A0.x, a1 = A0.y, a2 = A0.z, a3 = A0.w;
        float a4 = A1.x, a5 = A1.y, a6 = A1.z, a7 = A1.w;

        // gp(a, u), u grade-1 unit vector, Cl(3,0) shortlex
        float m0 = (a1 * ux + a2 * uy + a3 * uz) * w;
        float m1 = (a0 * ux + a4 * uy + a5 * uz) * w;
        float m2 = (a0 * uy + a6 * uz - a4 * ux) * w;
        float m3 = (a0 * uz - a5 * ux - a6 * uy) * w;
        float m4 = (a1 * uy + a7 * uz - a2 * ux) * w;
        float m5 = (a1 * uz - a3 * ux - a7 * uy) * w;
        float m6 = (a7 * ux - a3 * uy + a2 * uz) * w;
        float m7 = (a6 * ux - a5 * uy + a4 * uz) * w;

        float* p = g_agg + (size_t)sd.y * 128 + lane * 8;
        asm volatile("red.global.add.v4.f32 [%0], {%1,%2,%3,%4};"
                     :: "l"(p), "f"(m0), "f"(m1), "f"(m2), "f"(m3) : "memory");
        asm volatile("red.global.add.v4.f32 [%0], {%1,%2,%3,%4};"
                     :: "l"(p + 4), "f"(m4), "f"(m5), "f"(m6), "f"(m7) : "memory");
    }
}

// ---------------- node pass ----------------
__global__ void __launch_bounds__(128) node_kernel(
    const float* __restrict__ h,
    const float* __restrict__ Wout,
    const float* __restrict__ Wsgp,
    float* __restrict__ res,
    int N)
{
    __shared__ float s_a[1024];
    __shared__ float s_h[1024];
    __shared__ float s_wo[256];
    __shared__ float s_wq[256];

    int t = threadIdx.x;
    s_wo[t] = Wout[t];  s_wo[t + 128] = Wout[t + 128];
    s_wq[t] = Wsgp[t];  s_wq[t + 128] = Wsgp[t + 128];

    int basen = blockIdx.x * 8;
    int nvalid = min(8, N - basen);
    int f4count = nvalid * 32;

    const float4* ga = (const float4*)(g_agg + (size_t)basen * 128);
    const float4* gh = (const float4*)(h     + (size_t)basen * 128);
    float4* sa = (float4*)s_a;
    float4* sh = (float4*)s_h;
    if (t < f4count)       { sa[t]       = ga[t];       sh[t]       = gh[t]; }
    if (t + 128 < f4count) { sa[t + 128] = ga[t + 128]; sh[t + 128] = gh[t + 128]; }
    __syncthreads();

    int nl = t >> 4;
    if (basen + nl >= N) return;
    int o = t & 15;

    float a[8], q[8];
    #pragma unroll
    for (int i = 0; i < 8; i++) { a[i] = 0.f; q[i] = 0.f; }

    const float4* A4 = (const float4*)(s_a + nl * 128);
    const float4* H4 = (const float4*)(s_h + nl * 128);

    #pragma unroll
    for (int c = 0; c < 16; c++) {
        float wo = s_wo[c * 16 + o];
        float wq = s_wq[c * 16 + o];
        float4 x0 = A4[c * 2], x1 = A4[c * 2 + 1];
        float4 y0 = H4[c * 2], y1 = H4[c * 2 + 1];
        a[0] += x0.x * wo; a[1] += x0.y * wo; a[2] += x0.z * wo; a[3] += x0.w * wo;
        a[4] += x1.x * wo; a[5] += x1.y * wo; a[6] += x1.z * wo; a[7] += x1.w * wo;
        q[0] += y0.x * wq; q[1] += y0.y * wq; q[2] += y0.z * wq; q[3] += y0.w * wq;
        q[4] += y1.x * wq; q[5] += y1.y * wq; q[6] += y1.z * wq; q[7] += y1.w * wq;
    }

    float g0 = a[0]*q[0] + a[1]*q[1] + a[2]*q[2] + a[3]*q[3] - a[4]*q[4] - a[5]*q[5] - a[6]*q[6] - a[7]*q[7];
    float g1 = a[0]*q[1] + a[1]*q[0] - a[2]*q[4] - a[3]*q[5] + a[4]*q[2] + a[5]*q[3] - a[6]*q[7] - a[7]*q[6];
    float g2 = a[0]*q[2] + a[1]*q[4] + a[2]*q[0] - a[3]*q[6] - a[4]*q[1] + a[5]*q[7] + a[6]*q[3] + a[7]*q[5];
    float g3 = a[0]*q[3] + a[1]*q[5] + a[2]*q[6] + a[3]*q[0] - a[4]*q[7] - a[5]*q[1] - a[6]*q[2] - a[7]*q[4];
    float g4 = a[0]*q[4] + a[1]*q[2] - a[2]*q[1] + a[3]*q[7] + a[4]*q[0] - a[5]*q[6] + a[6]*q[5] + a[7]*q[3];
    float g5 = a[0]*q[5] + a[1]*q[3] - a[2]*q[7] - a[3]*q[1] + a[4]*q[6] + a[5]*q[0] - a[6]*q[4] - a[7]*q[2];
    float g6 = a[0]*q[6] + a[1]*q[7] + a[2]*q[3] - a[3]*q[2] - a[4]*q[5] + a[5]*q[4] + a[6]*q[0] + a[7]*q[1];
    float g7 = a[0]*q[7] + a[1]*q[6] - a[2]*q[5] + a[3]*q[4] + a[4]*q[3] - a[5]*q[2] + a[6]*q[1] + a[7]*q[0];

    float* op = res + (size_t)(basen + nl) * 128 + o * 8;
    ((float4*)op)[0] = make_float4(a[0] + g0, a[1] + g1, a[2] + g2, a[3] + g3);
    ((float4*)op)[1] = make_float4(a[4] + g4, a[5] + g5, a[6] + g6, a[7] + g7);
}

// ---------------- launch ----------------
extern "C" void kernel_launch(void* const* d_in, const int* in_sizes, int n_in,
                              void* d_out, int out_size)
{
    const float* h    = (const float*)d_in[0];
    const float* pos  = (const float*)d_in[1];
    const int*   ei   = (const int*)  d_in[2];
    const float* Wrbf = (const float*)d_in[3];
    const float* Wout = (const float*)d_in[4];
    const float* Wsgp = (const float*)d_in[5];
    float* out = (float*)d_out;

    int N = in_sizes[0] / 128;
    int E = in_sizes[2] / 2;
    if (N > MAXN) N = MAXN;
    if (E > MAXE) E = MAXE;

    // zero accumulator + survivor counter via memset nodes (graph-capturable)
    void* agg_ptr = nullptr;
    void* cnt_ptr = nullptr;
    cudaGetSymbolAddress(&agg_ptr, g_agg);
    cudaGetSymbolAddress(&cnt_ptr, g_cnt);
    cudaMemsetAsync(agg_ptr, 0, (size_t)N * 128 * sizeof(float), 0);
    cudaMemsetAsync(cnt_ptr, 0, sizeof(int), 0);

    filter_kernel<<<(E + 255) / 256, 256>>>(pos, ei, E);
    edge_kernel<<<2048, 256>>>(h, Wrbf);
    node_kernel<<<(N + 7) / 8, 128>>>(h, Wout, Wsgp, out, N);
}

// round 5
// speedup vs baseline: 1.2127x; 1.0952x over previous
#include <cuda_runtime.h>
#include <math.h>

// ---------------- problem constants ----------------
#define NRBF     32
#define CUTOFF_F 5.0f
#define GAMMA_F  40.96f                 // (NRBF/CUTOFF)^2
#define STEP_F   (5.0f / 31.0f)
#define INVSTEP_F (31.0f / 5.0f)
#define PI_F     3.14159265358979323846f
#define MAXN     50000
#define MAXE     800000

// scratch (static __device__ globals: allowed, no runtime alloc)
__device__ float  g_agg[(size_t)MAXN * 128];   // [N,16,8]
__device__ int    g_cnt;                       // survivor count
__device__ int2   g_sd[MAXE];                  // packed (src,dst)
__device__ float4 g_uvd[MAXE];                 // packed (ux,uy,uz,d)

// ---------------- filter + compact: 4 edges per thread ----------------
__global__ void __launch_bounds__(256) filter_kernel(
    const float* __restrict__ pos,
    const int*   __restrict__ ei,
    int E)
{
    int t = blockIdx.x * blockDim.x + threadIdx.x;
    int e0 = t * 4;

    int src[4], dst[4];
    bool live[4];
    float ux[4], uy[4], uz[4], dd[4];

    if (e0 + 3 < E) {
        int4 s4 = __ldg((const int4*)(ei + e0));
        int4 d4 = __ldg((const int4*)(ei + E + e0));
        src[0] = s4.x; src[1] = s4.y; src[2] = s4.z; src[3] = s4.w;
        dst[0] = d4.x; dst[1] = d4.y; dst[2] = d4.z; dst[3] = d4.w;
    } else {
        #pragma unroll
        for (int i = 0; i < 4; i++) {
            int e = e0 + i;
            src[i] = (e < E) ? ei[e] : 0;
            dst[i] = (e < E) ? ei[E + e] : 0;
        }
    }

    // 24 independent gathered loads -> high MLP
    float sx[4], sy[4], sz[4], dx[4], dy[4], dz[4];
    #pragma unroll
    for (int i = 0; i < 4; i++) {
        sx[i] = __ldg(pos + src[i] * 3 + 0);
        sy[i] = __ldg(pos + src[i] * 3 + 1);
        sz[i] = __ldg(pos + src[i] * 3 + 2);
        dx[i] = __ldg(pos + dst[i] * 3 + 0);
        dy[i] = __ldg(pos + dst[i] * 3 + 1);
        dz[i] = __ldg(pos + dst[i] * 3 + 2);
    }

    int cnt = 0;
    #pragma unroll
    for (int i = 0; i < 4; i++) {
        float rx = dx[i] - sx[i];
        float ry = dy[i] - sy[i];
        float rz = dz[i] - sz[i];
        float d = sqrtf(rx * rx + ry * ry + rz * rz + 1e-12f);
        bool ok = (e0 + i < E) && (d < CUTOFF_F);
        live[i] = ok;
        dd[i] = d;
        float inv = 1.0f / d;
        ux[i] = rx * inv; uy[i] = ry * inv; uz[i] = rz * inv;
        cnt += ok ? 1 : 0;
    }

    // warp-inclusive scan of per-thread counts
    int lane = threadIdx.x & 31;
    int incl = cnt;
    #pragma unroll
    for (int o = 1; o < 32; o <<= 1) {
        int v = __shfl_up_sync(0xFFFFFFFFu, incl, o);
        if (lane >= o) incl += v;
    }
    int total = __shfl_sync(0xFFFFFFFFu, incl, 31);
    if (!total) return;
    int base = 0;
    if (lane == 0) base = atomicAdd(&g_cnt, total);
    base = __shfl_sync(0xFFFFFFFFu, base, 0);

    int off = base + incl - cnt;
    #pragma unroll
    for (int i = 0; i < 4; i++) {
        if (live[i]) {
            g_sd[off]  = make_int2(src[i], dst[i]);
            g_uvd[off] = make_float4(ux[i], uy[i], uz[i], dd[i]);
            off++;
        }
    }
}

// ---------------- heavy edge pass: software-pipelined ----------------
// 16 threads per survivor (thread = channel); 256 threads/block.
__global__ void __launch_bounds__(256) edge_kernel(
    const float* __restrict__ h,
    const float* __restrict__ Wrbf)   // [32,16] row-major
{
    __shared__ float sW[NRBF * 16];
    int t = threadIdx.x;
    sW[t]       = Wrbf[t];
    sW[t + 256] = Wrbf[t + 256];
    __syncthreads();

    int cnt = g_cnt;
    int lane = t & 15;
    unsigned gbase = (unsigned)(t & 16);
    unsigned gmask = 0xFFFFu << gbase;
    int stride = gridDim.x * 16;

    int i = blockIdx.x * 16 + (t >> 4);
    if (i >= cnt) return;

    int2   sd  = __ldg(&g_sd[i]);
    float4 uvd = __ldg(&g_uvd[i]);

    while (true) {
        // start h-gather for current survivor immediately
        const float4* hp = (const float4*)(h + (size_t)sd.x * 128 + lane * 8);
        float4 A0 = __ldg(hp), A1 = __ldg(hp + 1);

        // prefetch next survivor's metadata (overlaps with current math)
        int inext = i + stride;
        int2 sdn; float4 uvdn;
        bool more = inext < cnt;
        if (more) { sdn = __ldg(&g_sd[inext]); uvdn = __ldg(&g_uvd[inext]); }

        float ux = uvd.x, uy = uvd.y, uz = uvd.z, d = uvd.w;

        // truncated gaussian smearing: 9 terms around d, cooperative exp
        int k0 = __float2int_rn(d * INVSTEP_F);
        k0 = min(max(k0, 0), 31);
        float r = 0.f;
        {
            int k = k0 + lane - 4;
            if (lane < 9 && k >= 0 && k <= 31) {
                float e = d - (float)k * STEP_F;
                r = __expf(-GAMMA_F * e * e);
            }
        }
        float w = 0.f;
        #pragma unroll
        for (int m = 0; m < 9; m++) {
            float rm = __shfl_sync(gmask, r, gbase + m, 32);
            int km = k0 + m - 4;
            int kc = min(max(km, 0), 31);
            w += rm * sW[kc * 16 + lane];
        }
        w *= 0.5f * (__cosf((PI_F / CUTOFF_F) * d) + 1.0f);

        float a0 = A0.x, a1 = A0.y, a2 = A0.z, a3 = A0.w;
        float a4 = A1.x, a5 = A1.y, a6 = A1.z, a7 = A1.w;

        // gp(a, u), u grade-1 unit vector, Cl(3,0) shortlex
        float m0 = (a1 * ux + a2 * uy + a3 * uz) * w;
        float m1 = (a0 * ux + a4 * uy + a5 * uz) * w;
        float m2 = (a0 * uy + a6 * uz - a4 * ux) * w;
        float m3 = (a0 * uz - a5 * ux - a6 * uy) * w;
        float m4 = (a1 * uy + a7 * uz - a2 * ux) * w;
        float m5 = (a1 * uz - a3 * ux - a7 * uy) * w;
        float m6 = (a7 * ux - a3 * uy + a2 * uz) * w;
        float m7 = (a6 * ux - a5 * uy + a4 * uz) * w;

        float* p = g_agg + (size_t)sd.y * 128 + lane * 8;
        asm volatile("red.global.add.v4.f32 [%0], {%1,%2,%3,%4};"
                     :: "l"(p), "f"(m0), "f"(m1), "f"(m2), "f"(m3) : "memory");
        asm volatile("red.global.add.v4.f32 [%0], {%1,%2,%3,%4};"
                     :: "l"(p + 4), "f"(m4), "f"(m5), "f"(m6), "f"(m7) : "memory");

        if (!more) break;
        sd = sdn; uvd = uvdn; i = inext;
    }
}

// ---------------- node pass ----------------
__global__ void __launch_bounds__(128) node_kernel(
    const float* __restrict__ h,
    const float* __restrict__ Wout,
    const float* __restrict__ Wsgp,
    float* __restrict__ res,
    int N)
{
    __shared__ float s_a[1024];
    __shared__ float s_h[1024];
    __shared__ float s_wo[256];
    __shared__ float s_wq[256];

    int t = threadIdx.x;
    s_wo[t] = Wout[t];  s_wo[t + 128] = Wout[t + 128];
    s_wq[t] = Wsgp[t];  s_wq[t + 128] = Wsgp[t + 128];

    int basen = blockIdx.x * 8;
    int nvalid = min(8, N - basen);
    int f4count = nvalid * 32;

    const float4* ga = (const float4*)(g_agg + (size_t)basen * 128);
    const float4* gh = (const float4*)(h     + (size_t)basen * 128);
    float4* sa = (float4*)s_a;
    float4* sh = (float4*)s_h;
    if (t < f4count)       { sa[t]       = ga[t];       sh[t]       = gh[t]; }
    if (t + 128 < f4count) { sa[t + 128] = ga[t + 128]; sh[t + 128] = gh[t + 128]; }
    __syncthreads();

    int nl = t >> 4;
    if (basen + nl >= N) return;
    int o = t & 15;

    float a[8], q[8];
    #pragma unroll
    for (int i = 0; i < 8; i++) { a[i] = 0.f; q[i] = 0.f; }

    const float4* A4 = (const float4*)(s_a + nl * 128);
    const float4* H4 = (const float4*)(s_h + nl * 128);

    #pragma unroll
    for (int c = 0; c < 16; c++) {
        float wo = s_wo[c * 16 + o];
        float wq = s_wq[c * 16 + o];
        float4 x0 = A4[c * 2], x1 = A4[c * 2 + 1];
        float4 y0 = H4[c * 2], y1 = H4[c * 2 + 1];
        a[0] += x0.x * wo; a[1] += x0.y * wo; a[2] += x0.z * wo; a[3] += x0.w * wo;
        a[4] += x1.x * wo; a[5] += x1.y * wo; a[6] += x1.z * wo; a[7] += x1.w * wo;
        q[0] += y0.x * wq; q[1] += y0.y * wq; q[2] += y0.z * wq; q[3] += y0.w * wq;
        q[4] += y1.x * wq; q[5] += y1.y * wq; q[6] += y1.z * wq; q[7] += y1.w * wq;
    }

    float g0 = a[0]*q[0] + a[1]*q[1] + a[2]*q[2] + a[3]*q[3] - a[4]*q[4] - a[5]*q[5] - a[6]*q[6] - a[7]*q[7];
    float g1 = a[0]*q[1] + a[1]*q[0] - a[2]*q[4] - a[3]*q[5] + a[4]*q[2] + a[5]*q[3] - a[6]*q[7] - a[7]*q[6];
    float g2 = a[0]*q[2] + a[1]*q[4] + a[2]*q[0] - a[3]*q[6] - a[4]*q[1] + a[5]*q[7] + a[6]*q[3] + a[7]*q[5];
    float g3 = a[0]*q[3] + a[1]*q[5] + a[2]*q[6] + a[3]*q[0] - a[4]*q[7] - a[5]*q[1] - a[6]*q[2] - a[7]*q[4];
    float g4 = a[0]*q[4] + a[1]*q[2] - a[2]*q[1] + a[3]*q[7] + a[4]*q[0] - a[5]*q[6] + a[6]*q[5] + a[7]*q[3];
    float g5 = a[0]*q[5] + a[1]*q[3] - a[2]*q[7] - a[3]*q[1] + a[4]*q[6] + a[5]*q[0] - a[6]*q[4] - a[7]*q[2];
    float g6 = a[0]*q[6] + a[1]*q[7] + a[2]*q[3] - a[3]*q[2] - a[4]*q[5] + a[5]*q[4] + a[6]*q[0] + a[7]*q[1];
    float g7 = a[0]*q[7] + a[1]*q[6] - a[2]*q[5] + a[3]*q[4] + a[4]*q[3] - a[5]*q[2] + a[6]*q[1] + a[7]*q[0];

    float* op = res + (size_t)(basen + nl) * 128 + o * 8;
    ((float4*)op)[0] = make_float4(a[0] + g0, a[1] + g1, a[2] + g2, a[3] + g3);
    ((float4*)op)[1] = make_float4(a[4] + g4, a[5] + g5, a[6] + g6, a[7] + g7);
}

// ---------------- launch ----------------
extern "C" void kernel_launch(void* const* d_in, const int* in_sizes, int n_in,
                              void* d_out, int out_size)
{
    const float* h    = (const float*)d_in[0];
    const float* pos  = (const float*)d_in[1];
    const int*   ei   = (const int*)  d_in[2];
    const float* Wrbf = (const float*)d_in[3];
    const float* Wout = (const float*)d_in[4];
    const float* Wsgp = (const float*)d_in[5];
    float* out = (float*)d_out;

    int N = in_sizes[0] / 128;
    int E = in_sizes[2] / 2;
    if (N > MAXN) N = MAXN;
    if (E > MAXE) E = MAXE;

    void* agg_ptr = nullptr;
    void* cnt_ptr = nullptr;
    cudaGetSymbolAddress(&agg_ptr, g_agg);
    cudaGetSymbolAddress(&cnt_ptr, g_cnt);
    cudaMemsetAsync(agg_ptr, 0, (size_t)N * 128 * sizeof(float), 0);
    cudaMemsetAsync(cnt_ptr, 0, sizeof(int), 0);

    int nthreads = (E + 3) / 4;
    filter_kernel<<<(nthreads + 255) / 256, 256>>>(pos, ei, E);
    edge_kernel<<<2048, 256>>>(h, Wrbf);
    node_kernel<<<(N + 7) / 8, 128>>>(h, Wout, Wsgp, out, N);
}

// round 6
// speedup vs baseline: 1.3408x; 1.1057x over previous
#include <cuda_runtime.h>
#include <math.h>

// ---------------- problem constants ----------------
#define NRBF     32
#define CUTOFF_F 5.0f
#define GAMMA_F  40.96f                 // (NRBF/CUTOFF)^2
#define STEP_F   (5.0f / 31.0f)
#define INVSTEP_F (31.0f / 5.0f)
#define PI_F     3.14159265358979323846f
#define MAXN     50000

// scratch accumulator [N,16,8]
__device__ float g_agg[(size_t)MAXN * 128];

// ---------------- fused filter + edge pass ----------------
// One warp takes 32 raw edges (lane = edge): computes distances, ballots
// survivors, then processes survivors 2-at-a-time (16 lanes per survivor).
__global__ void __launch_bounds__(256) edge_fused_kernel(
    const float* __restrict__ h,
    const float* __restrict__ pos,
    const int*   __restrict__ ei,
    const float* __restrict__ Wrbf,   // [32,16] row-major
    int E)
{
    __shared__ float sW[NRBF * 16];
    int t = threadIdx.x;
    sW[t]       = Wrbf[t];
    sW[t + 256] = Wrbf[t + 256];
    __syncthreads();

    const unsigned FULL = 0xFFFFFFFFu;
    int lane  = t & 31;
    int hlane = t & 15;                      // channel within half-warp
    unsigned gbase = (unsigned)(t & 16);     // 0 or 16
    unsigned gmask = 0xFFFFu << gbase;       // this half-warp's shfl mask
    int half  = (t >> 4) & 1;

    // ---- filter phase: 1 edge per lane ----
    int e = (blockIdx.x * 8 + (t >> 5)) * 32 + lane;
    bool valid = e < E;
    int src = 0, dst = 0;
    if (valid) { src = __ldg(ei + e); dst = __ldg(ei + E + e); }

    float rx = 0.f, ry = 0.f, rz = 0.f;
    if (valid) {
        rx = __ldg(pos + dst * 3 + 0) - __ldg(pos + src * 3 + 0);
        ry = __ldg(pos + dst * 3 + 1) - __ldg(pos + src * 3 + 1);
        rz = __ldg(pos + dst * 3 + 2) - __ldg(pos + src * 3 + 2);
    }
    float d = sqrtf(rx * rx + ry * ry + rz * rz + 1e-12f);
    bool live = valid && (d < CUTOFF_F);
    float inv = 1.0f / d;
    float ux = rx * inv, uy = ry * inv, uz = rz * inv;

    unsigned mask = __ballot_sync(FULL, live);

    // ---- heavy phase: 2 survivors per iteration, 16 lanes each ----
    while (mask) {
        int s0 = __ffs(mask) - 1;
        unsigned m2 = mask & (mask - 1);
        int s1 = m2 ? (__ffs(m2) - 1) : 32;       // 32 = invalid
        mask = m2 ? (m2 & (m2 - 1)) : 0u;

        int sl = half ? s1 : s0;
        bool act = sl < 32;
        int srcl = sl & 31;

        int   ssrc = __shfl_sync(FULL, src, srcl);
        int   sdst = __shfl_sync(FULL, dst, srcl);
        float sux  = __shfl_sync(FULL, ux,  srcl);
        float suy  = __shfl_sync(FULL, uy,  srcl);
        float suz  = __shfl_sync(FULL, uz,  srcl);
        float sd   = __shfl_sync(FULL, d,   srcl);

        if (act) {
            // gather h[src], channel = hlane (starts immediately)
            const float4* hp = (const float4*)(h + (size_t)ssrc * 128 + hlane * 8);
            float4 A0 = __ldg(hp), A1 = __ldg(hp + 1);

            // truncated gaussian smearing: 9 terms around sd, cooperative exp
            int k0 = __float2int_rn(sd * INVSTEP_F);
            k0 = min(max(k0, 0), 31);
            float r = 0.f;
            {
                int k = k0 + hlane - 4;
                if (hlane < 9 && k >= 0 && k <= 31) {
                    float dd = sd - (float)k * STEP_F;
                    r = __expf(-GAMMA_F * dd * dd);
                }
            }
            float w = 0.f;
            #pragma unroll
            for (int m = 0; m < 9; m++) {
                float rm = __shfl_sync(gmask, r, gbase + m, 32);
                int km = k0 + m - 4;
                int kc = min(max(km, 0), 31);
                w += rm * sW[kc * 16 + hlane];
            }
            w *= 0.5f * (__cosf((PI_F / CUTOFF_F) * sd) + 1.0f);

            // fold w into the direction vector (per-channel)
            float wx = w * sux, wy = w * suy, wz = w * suz;

            float a0 = A0.x, a1 = A0.y, a2 = A0.z, a3 = A0.w;
            float a4 = A1.x, a5 = A1.y, a6 = A1.z, a7 = A1.w;

            // gp(a, u)*w, Cl(3,0) shortlex
            float m0 = a1 * wx + a2 * wy + a3 * wz;
            float m1 = a0 * wx + a4 * wy + a5 * wz;
            float m2v= a0 * wy + a6 * wz - a4 * wx;
            float m3 = a0 * wz - a5 * wx - a6 * wy;
            float m4 = a1 * wy + a7 * wz - a2 * wx;
            float m5 = a1 * wz - a3 * wx - a7 * wy;
            float m6 = a7 * wx - a3 * wy + a2 * wz;
            float m7 = a6 * wx - a5 * wy + a4 * wz;

            float* p = g_agg + (size_t)sdst * 128 + hlane * 8;
            asm volatile("red.global.add.v4.f32 [%0], {%1,%2,%3,%4};"
                         :: "l"(p), "f"(m0), "f"(m1), "f"(m2v), "f"(m3) : "memory");
            asm volatile("red.global.add.v4.f32 [%0], {%1,%2,%3,%4};"
                         :: "l"(p + 4), "f"(m4), "f"(m5), "f"(m6), "f"(m7) : "memory");
        }
    }
}

// ---------------- node pass ----------------
__global__ void __launch_bounds__(128) node_kernel(
    const float* __restrict__ h,
    const float* __restrict__ Wout,
    const float* __restrict__ Wsgp,
    float* __restrict__ res,
    int N)
{
    __shared__ float s_a[1024];
    __shared__ float s_h[1024];
    __shared__ float s_wo[256];
    __shared__ float s_wq[256];

    int t = threadIdx.x;
    s_wo[t] = Wout[t];  s_wo[t + 128] = Wout[t + 128];
    s_wq[t] = Wsgp[t];  s_wq[t + 128] = Wsgp[t + 128];

    int basen = blockIdx.x * 8;
    int nvalid = min(8, N - basen);
    int f4count = nvalid * 32;

    const float4* ga = (const float4*)(g_agg + (size_t)basen * 128);
    const float4* gh = (const float4*)(h     + (size_t)basen * 128);
    float4* sa = (float4*)s_a;
    float4* sh = (float4*)s_h;
    if (t < f4count)       { sa[t]       = ga[t];       sh[t]       = gh[t]; }
    if (t + 128 < f4count) { sa[t + 128] = ga[t + 128]; sh[t + 128] = gh[t + 128]; }
    __syncthreads();

    int nl = t >> 4;
    if (basen + nl >= N) return;
    int o = t & 15;

    float a[8], q[8];
    #pragma unroll
    for (int i = 0; i < 8; i++) { a[i] = 0.f; q[i] = 0.f; }

    const float4* A4 = (const float4*)(s_a + nl * 128);
    const float4* H4 = (const float4*)(s_h + nl * 128);

    #pragma unroll
    for (int c = 0; c < 16; c++) {
        float wo = s_wo[c * 16 + o];
        float wq = s_wq[c * 16 + o];
        float4 x0 = A4[c * 2], x1 = A4[c * 2 + 1];
        float4 y0 = H4[c * 2], y1 = H4[c * 2 + 1];
        a[0] += x0.x * wo; a[1] += x0.y * wo; a[2] += x0.z * wo; a[3] += x0.w * wo;
        a[4] += x1.x * wo; a[5] += x1.y * wo; a[6] += x1.z * wo; a[7] += x1.w * wo;
        q[0] += y0.x * wq; q[1] += y0.y * wq; q[2] += y0.z * wq; q[3] += y0.w * wq;
        q[4] += y1.x * wq; q[5] += y1.y * wq; q[6] += y1.z * wq; q[7] += y1.w * wq;
    }

    float g0 = a[0]*q[0] + a[1]*q[1] + a[2]*q[2] + a[3]*q[3] - a[4]*q[4] - a[5]*q[5] - a[6]*q[6] - a[7]*q[7];
    float g1 = a[0]*q[1] + a[1]*q[0] - a[2]*q[4] - a[3]*q[5] + a[4]*q[2] + a[5]*q[3] - a[6]*q[7] - a[7]*q[6];
    float g2 = a[0]*q[2] + a[1]*q[4] + a[2]*q[0] - a[3]*q[6] - a[4]*q[1] + a[5]*q[7] + a[6]*q[3] + a[7]*q[5];
    float g3 = a[0]*q[3] + a[1]*q[5] + a[2]*q[6] + a[3]*q[0] - a[4]*q[7] - a[5]*q[1] - a[6]*q[2] - a[7]*q[4];
    float g4 = a[0]*q[4] + a[1]*q[2] - a[2]*q[1] + a[3]*q[7] + a[4]*q[0] - a[5]*q[6] + a[6]*q[5] + a[7]*q[3];
    float g5 = a[0]*q[5] + a[1]*q[3] - a[2]*q[7] - a[3]*q[1] + a[4]*q[6] + a[5]*q[0] - a[6]*q[4] - a[7]*q[2];
    float g6 = a[0]*q[6] + a[1]*q[7] + a[2]*q[3] - a[3]*q[2] - a[4]*q[5] + a[5]*q[4] + a[6]*q[0] + a[7]*q[1];
    float g7 = a[0]*q[7] + a[1]*q[6] - a[2]*q[5] + a[3]*q[4] + a[4]*q[3] - a[5]*q[2] + a[6]*q[1] + a[7]*q[0];

    float* op = res + (size_t)(basen + nl) * 128 + o * 8;
    ((float4*)op)[0] = make_float4(a[0] + g0, a[1] + g1, a[2] + g2, a[3] + g3);
    ((float4*)op)[1] = make_float4(a[4] + g4, a[5] + g5, a[6] + g6, a[7] + g7);
}

// ---------------- launch ----------------
extern "C" void kernel_launch(void* const* d_in, const int* in_sizes, int n_in,
                              void* d_out, int out_size)
{
    const float* h    = (const float*)d_in[0];
    const float* pos  = (const float*)d_in[1];
    const int*   ei   = (const int*)  d_in[2];
    const float* Wrbf = (const float*)d_in[3];
    const float* Wout = (const float*)d_in[4];
    const float* Wsgp = (const float*)d_in[5];
    float* out = (float*)d_out;

    int N = in_sizes[0] / 128;
    int E = in_sizes[2] / 2;
    if (N > MAXN) N = MAXN;

    void* agg_ptr = nullptr;
    cudaGetSymbolAddress(&agg_ptr, g_agg);
    cudaMemsetAsync(agg_ptr, 0, (size_t)N * 128 * sizeof(float), 0);

    // one warp per 32 edges, 8 warps per block
    int blocks = (E + 255) / 256;
    edge_fused_kernel<<<blocks, 256>>>(h, pos, ei, Wrbf, E);
    node_kernel<<<(N + 7) / 8, 128>>>(h, Wout, Wsgp, out, N);
}

// round 7
// speedup vs baseline: 1.3815x; 1.0303x over previous
#include <cuda_runtime.h>
#include <math.h>

// ---------------- problem constants ----------------
#define NRBF     32
#define CUTOFF_F 5.0f
#define GAMMA_F  40.96f                 // (NRBF/CUTOFF)^2
#define STEP_F   (5.0f / 31.0f)
#define INVSTEP_F (31.0f / 5.0f)
#define PI_F     3.14159265358979323846f
#define MAXN     50000

// scratch accumulator [N,16,8]
__device__ float g_agg[(size_t)MAXN * 128];

// ---------------- f32x2 packed helpers (FFMA2 path, sm_100+) ----------------
__device__ __forceinline__ unsigned long long pack2(float lo, float hi) {
    unsigned long long r;
    asm("mov.b64 %0, {%1, %2};" : "=l"(r) : "f"(lo), "f"(hi));
    return r;
}
__device__ __forceinline__ void unpack2(unsigned long long v, float& lo, float& hi) {
    asm("mov.b64 {%0, %1}, %2;" : "=f"(lo), "=f"(hi) : "l"(v));
}
__device__ __forceinline__ void fma2(unsigned long long& d,
                                     unsigned long long a,
                                     unsigned long long b) {
    asm("fma.rn.f32x2 %0, %1, %2, %3;" : "=l"(d) : "l"(a), "l"(b), "l"(d));
}

// ---------------- fused filter + edge pass ----------------
// One warp takes 32 raw edges (lane = edge): computes distances, ballots
// survivors, then processes survivors 2-at-a-time (16 lanes per survivor).
__global__ void __launch_bounds__(256) edge_fused_kernel(
    const float* __restrict__ h,
    const float* __restrict__ pos,
    const int*   __restrict__ ei,
    const float* __restrict__ Wrbf,   // [32,16] row-major
    int E)
{
    __shared__ float sW[NRBF * 16];
    int t = threadIdx.x;
    sW[t]       = Wrbf[t];
    sW[t + 256] = Wrbf[t + 256];
    __syncthreads();

    const unsigned FULL = 0xFFFFFFFFu;
    int lane  = t & 31;
    int hlane = t & 15;
    unsigned gbase = (unsigned)(t & 16);
    unsigned gmask = 0xFFFFu << gbase;
    int half  = (t >> 4) & 1;

    // ---- filter phase: 1 edge per lane ----
    int e = (blockIdx.x * 8 + (t >> 5)) * 32 + lane;
    bool valid = e < E;
    int src = 0, dst = 0;
    if (valid) { src = __ldg(ei + e); dst = __ldg(ei + E + e); }

    float rx = 0.f, ry = 0.f, rz = 0.f;
    if (valid) {
        rx = __ldg(pos + dst * 3 + 0) - __ldg(pos + src * 3 + 0);
        ry = __ldg(pos + dst * 3 + 1) - __ldg(pos + src * 3 + 1);
        rz = __ldg(pos + dst * 3 + 2) - __ldg(pos + src * 3 + 2);
    }
    float d = sqrtf(rx * rx + ry * ry + rz * rz + 1e-12f);
    bool live = valid && (d < CUTOFF_F);
    float inv = 1.0f / d;
    float ux = rx * inv, uy = ry * inv, uz = rz * inv;

    unsigned mask = __ballot_sync(FULL, live);

    // ---- heavy phase: 2 survivors per iteration, 16 lanes each ----
    while (mask) {
        int s0 = __ffs(mask) - 1;
        unsigned m2 = mask & (mask - 1);
        int s1 = m2 ? (__ffs(m2) - 1) : 32;
        mask = m2 ? (m2 & (m2 - 1)) : 0u;

        int sl = half ? s1 : s0;
        bool act = sl < 32;
        int srcl = sl & 31;

        int   ssrc = __shfl_sync(FULL, src, srcl);
        int   sdst = __shfl_sync(FULL, dst, srcl);
        float sux  = __shfl_sync(FULL, ux,  srcl);
        float suy  = __shfl_sync(FULL, uy,  srcl);
        float suz  = __shfl_sync(FULL, uz,  srcl);
        float sd   = __shfl_sync(FULL, d,   srcl);

        if (act) {
            const float4* hp = (const float4*)(h + (size_t)ssrc * 128 + hlane * 8);
            float4 A0 = __ldg(hp), A1 = __ldg(hp + 1);

            int k0 = __float2int_rn(sd * INVSTEP_F);
            k0 = min(max(k0, 0), 31);
            float r = 0.f;
            {
                int k = k0 + hlane - 4;
                if (hlane < 9 && k >= 0 && k <= 31) {
                    float dd = sd - (float)k * STEP_F;
                    r = __expf(-GAMMA_F * dd * dd);
                }
            }
            float w = 0.f;
            #pragma unroll
            for (int m = 0; m < 9; m++) {
                float rm = __shfl_sync(gmask, r, gbase + m, 32);
                int km = k0 + m - 4;
                int kc = min(max(km, 0), 31);
                w += rm * sW[kc * 16 + hlane];
            }
            w *= 0.5f * (__cosf((PI_F / CUTOFF_F) * sd) + 1.0f);

            float wx = w * sux, wy = w * suy, wz = w * suz;

            float a0 = A0.x, a1 = A0.y, a2 = A0.z, a3 = A0.w;
            float a4 = A1.x, a5 = A1.y, a6 = A1.z, a7 = A1.w;

            float m0 = a1 * wx + a2 * wy + a3 * wz;
            float m1 = a0 * wx + a4 * wy + a5 * wz;
            float m2v= a0 * wy + a6 * wz - a4 * wx;
            float m3 = a0 * wz - a5 * wx - a6 * wy;
            float m4 = a1 * wy + a7 * wz - a2 * wx;
            float m5 = a1 * wz - a3 * wx - a7 * wy;
            float m6 = a7 * wx - a3 * wy + a2 * wz;
            float m7 = a6 * wx - a5 * wy + a4 * wz;

            float* p = g_agg + (size_t)sdst * 128 + hlane * 8;
            asm volatile("red.global.add.v4.f32 [%0], {%1,%2,%3,%4};"
                         :: "l"(p), "f"(m0), "f"(m1), "f"(m2v), "f"(m3) : "memory");
            asm volatile("red.global.add.v4.f32 [%0], {%1,%2,%3,%4};"
                         :: "l"(p + 4), "f"(m4), "f"(m5), "f"(m6), "f"(m7) : "memory");
        }
    }
}

// ---------------- node pass: 16 nodes/block, padded smem, f32x2 FMA ----------------
#define NODE_STRIDE 136   // floats; 544B: 16B-aligned, +8 banks between nodes

__global__ void __launch_bounds__(256) node_kernel(
    const float* __restrict__ h,
    const float* __restrict__ Wout,   // [16,16] row-major W[c*16+o]
    const float* __restrict__ Wsgp,
    float* __restrict__ res,
    int N)
{
    __shared__ float s_a[16 * NODE_STRIDE];
    __shared__ float s_h[16 * NODE_STRIDE];
    __shared__ float s_wo[256];
    __shared__ float s_wq[256];

    int t = threadIdx.x;
    s_wo[t] = Wout[t];
    s_wq[t] = Wsgp[t];

    int basen = blockIdx.x * 16;
    int nv4 = min(16, N - basen) * 32;   // float4s to stage per array

    const float4* ga = (const float4*)(g_agg + (size_t)basen * 128);
    const float4* gh = (const float4*)(h     + (size_t)basen * 128);
    #pragma unroll
    for (int k = 0; k < 2; k++) {
        int idx = t + k * 256;
        if (idx < nv4) {
            int node  = idx >> 5;
            int inner = idx & 31;
            float4 va = __ldg(ga + idx);
            float4 vh = __ldg(gh + idx);
            *(float4*)&s_a[node * NODE_STRIDE + inner * 4] = va;
            *(float4*)&s_h[node * NODE_STRIDE + inner * 4] = vh;
        }
    }
    __syncthreads();

    int nl = t >> 4;
    int node = basen + nl;
    if (node >= N) return;
    int o = t & 15;

    unsigned long long a2[4], q2[4];
    unsigned long long z = pack2(0.f, 0.f);
    #pragma unroll
    for (int i = 0; i < 4; i++) { a2[i] = z; q2[i] = z; }

    const float* A = s_a + nl * NODE_STRIDE;
    const float* H = s_h + nl * NODE_STRIDE;

    #pragma unroll
    for (int c = 0; c < 16; c++) {
        float wo = s_wo[c * 16 + o];
        float wq = s_wq[c * 16 + o];
        unsigned long long wo2 = pack2(wo, wo);
        unsigned long long wq2 = pack2(wq, wq);
        const float4* x = (const float4*)(A + c * 8);
        const float4* y = (const float4*)(H + c * 8);
        float4 x0 = x[0], x1 = x[1];
        float4 y0 = y[0], y1 = y[1];
        fma2(a2[0], pack2(x0.x, x0.y), wo2);
        fma2(a2[1], pack2(x0.z, x0.w), wo2);
        fma2(a2[2], pack2(x1.x, x1.y), wo2);
        fma2(a2[3], pack2(x1.z, x1.w), wo2);
        fma2(q2[0], pack2(y0.x, y0.y), wq2);
        fma2(q2[1], pack2(y0.z, y0.w), wq2);
        fma2(q2[2], pack2(y1.x, y1.y), wq2);
        fma2(q2[3], pack2(y1.z, y1.w), wq2);
    }

    float a[8], q[8];
    #pragma unroll
    for (int i = 0; i < 4; i++) {
        unpack2(a2[i], a[2 * i], a[2 * i + 1]);
        unpack2(q2[i], q[2 * i], q[2 * i + 1]);
    }

    // full Cl(3,0) geometric product g = gp(a, q)
    float g0 = a[0]*q[0] + a[1]*q[1] + a[2]*q[2] + a[3]*q[3] - a[4]*q[4] - a[5]*q[5] - a[6]*q[6] - a[7]*q[7];
    float g1 = a[0]*q[1] + a[1]*q[0] - a[2]*q[4] - a[3]*q[5] + a[4]*q[2] + a[5]*q[3] - a[6]*q[7] - a[7]*q[6];
    float g2 = a[0]*q[2] + a[1]*q[4] + a[2]*q[0] - a[3]*q[6] - a[4]*q[1] + a[5]*q[7] + a[6]*q[3] + a[7]*q[5];
    float g3 = a[0]*q[3] + a[1]*q[5] + a[2]*q[6] + a[3]*q[0] - a[4]*q[7] - a[5]*q[1] - a[6]*q[2] - a[7]*q[4];
    float g4 = a[0]*q[4] + a[1]*q[2] - a[2]*q[1] + a[3]*q[7] + a[4]*q[0] - a[5]*q[6] + a[6]*q[5] + a[7]*q[3];
    float g5 = a[0]*q[5] + a[1]*q[3] - a[2]*q[7] - a[3]*q[1] + a[4]*q[6] + a[5]*q[0] - a[6]*q[4] - a[7]*q[2];
    float g6 = a[0]*q[6] + a[1]*q[7] + a[2]*q[3] - a[3]*q[2] - a[4]*q[5] + a[5]*q[4] + a[6]*q[0] + a[7]*q[1];
    float g7 = a[0]*q[7] + a[1]*q[6] - a[2]*q[5] + a[3]*q[4] + a[4]*q[3] - a[5]*q[2] + a[6]*q[1] + a[7]*q[0];

    float* op = res + (size_t)node * 128 + o * 8;
    ((float4*)op)[0] = make_float4(a[0] + g0, a[1] + g1, a[2] + g2, a[3] + g3);
    ((float4*)op)[1] = make_float4(a[4] + g4, a[5] + g5, a[6] + g6, a[7] + g7);
}

// ---------------- launch ----------------
extern "C" void kernel_launch(void* const* d_in, const int* in_sizes, int n_in,
                              void* d_out, int out_size)
{
    const float* h    = (const float*)d_in[0];
    const float* pos  = (const float*)d_in[1];
    const int*   ei   = (const int*)  d_in[2];
    const float* Wrbf = (const float*)d_in[3];
    const float* Wout = (const float*)d_in[4];
    const float* Wsgp = (const float*)d_in[5];
    float* out = (float*)d_out;

    int N = in_sizes[0] / 128;
    int E = in_sizes[2] / 2;
    if (N > MAXN) N = MAXN;

    void* agg_ptr = nullptr;
    cudaGetSymbolAddress(&agg_ptr, g_agg);
    cudaMemsetAsync(agg_ptr, 0, (size_t)N * 128 * sizeof(float), 0);

    int blocks = (E + 255) / 256;
    edge_fused_kernel<<<blocks, 256>>>(h, pos, ei, Wrbf, E);
    node_kernel<<<(N + 15) / 16, 256>>>(h, Wout, Wsgp, out, N);
}

// round 8
// speedup vs baseline: 1.4556x; 1.0536x over previous
#include <cuda_runtime.h>
#include <math.h>

// ---------------- problem constants ----------------
#define NRBF     32
#define CUTOFF_F 5.0f
#define GAMMA_F  40.96f                 // (NRBF/CUTOFF)^2
#define STEP_F   (5.0f / 31.0f)
#define INVSTEP_F (31.0f / 5.0f)
#define PI_F     3.14159265358979323846f
#define MAXN     50000

// scratch accumulator [N,16,8]
__device__ float g_agg[(size_t)MAXN * 128];

// ---------------- f32x2 packed helpers (FFMA2 path, sm_100+) ----------------
__device__ __forceinline__ unsigned long long pack2(float lo, float hi) {
    unsigned long long r;
    asm("mov.b64 %0, {%1, %2};" : "=l"(r) : "f"(lo), "f"(hi));
    return r;
}
__device__ __forceinline__ void unpack2(unsigned long long v, float& lo, float& hi) {
    asm("mov.b64 {%0, %1}, %2;" : "=f"(lo), "=f"(hi) : "l"(v));
}
__device__ __forceinline__ void fma2(unsigned long long& d,
                                     unsigned long long a,
                                     unsigned long long b) {
    asm("fma.rn.f32x2 %0, %1, %2, %3;" : "=l"(d) : "l"(a), "l"(b), "l"(d));
}

// ---------------- fused filter + edge pass (unchanged) ----------------
__global__ void __launch_bounds__(256) edge_fused_kernel(
    const float* __restrict__ h,
    const float* __restrict__ pos,
    const int*   __restrict__ ei,
    const float* __restrict__ Wrbf,   // [32,16] row-major
    int E)
{
    __shared__ float sW[NRBF * 16];
    int t = threadIdx.x;
    sW[t]       = Wrbf[t];
    sW[t + 256] = Wrbf[t + 256];
    __syncthreads();

    const unsigned FULL = 0xFFFFFFFFu;
    int lane  = t & 31;
    int hlane = t & 15;
    unsigned gbase = (unsigned)(t & 16);
    unsigned gmask = 0xFFFFu << gbase;
    int half  = (t >> 4) & 1;

    int e = (blockIdx.x * 8 + (t >> 5)) * 32 + lane;
    bool valid = e < E;
    int src = 0, dst = 0;
    if (valid) { src = __ldg(ei + e); dst = __ldg(ei + E + e); }

    float rx = 0.f, ry = 0.f, rz = 0.f;
    if (valid) {
        rx = __ldg(pos + dst * 3 + 0) - __ldg(pos + src * 3 + 0);
        ry = __ldg(pos + dst * 3 + 1) - __ldg(pos + src * 3 + 1);
        rz = __ldg(pos + dst * 3 + 2) - __ldg(pos + src * 3 + 2);
    }
    float d = sqrtf(rx * rx + ry * ry + rz * rz + 1e-12f);
    bool live = valid && (d < CUTOFF_F);
    float inv = 1.0f / d;
    float ux = rx * inv, uy = ry * inv, uz = rz * inv;

    unsigned mask = __ballot_sync(FULL, live);

    while (mask) {
        int s0 = __ffs(mask) - 1;
        unsigned m2 = mask & (mask - 1);
        int s1 = m2 ? (__ffs(m2) - 1) : 32;
        mask = m2 ? (m2 & (m2 - 1)) : 0u;

        int sl = half ? s1 : s0;
        bool act = sl < 32;
        int srcl = sl & 31;

        int   ssrc = __shfl_sync(FULL, src, srcl);
        int   sdst = __shfl_sync(FULL, dst, srcl);
        float sux  = __shfl_sync(FULL, ux,  srcl);
        float suy  = __shfl_sync(FULL, uy,  srcl);
        float suz  = __shfl_sync(FULL, uz,  srcl);
        float sd   = __shfl_sync(FULL, d,   srcl);

        if (act) {
            const float4* hp = (const float4*)(h + (size_t)ssrc * 128 + hlane * 8);
            float4 A0 = __ldg(hp), A1 = __ldg(hp + 1);

            int k0 = __float2int_rn(sd * INVSTEP_F);
            k0 = min(max(k0, 0), 31);
            float r = 0.f;
            {
                int k = k0 + hlane - 4;
                if (hlane < 9 && k >= 0 && k <= 31) {
                    float dd = sd - (float)k * STEP_F;
                    r = __expf(-GAMMA_F * dd * dd);
                }
            }
            float w = 0.f;
            #pragma unroll
            for (int m = 0; m < 9; m++) {
                float rm = __shfl_sync(gmask, r, gbase + m, 32);
                int km = k0 + m - 4;
                int kc = min(max(km, 0), 31);
                w += rm * sW[kc * 16 + hlane];
            }
            w *= 0.5f * (__cosf((PI_F / CUTOFF_F) * sd) + 1.0f);

            float wx = w * sux, wy = w * suy, wz = w * suz;

            float a0 = A0.x, a1 = A0.y, a2 = A0.z, a3 = A0.w;
            float a4 = A1.x, a5 = A1.y, a6 = A1.z, a7 = A1.w;

            float m0 = a1 * wx + a2 * wy + a3 * wz;
            float m1 = a0 * wx + a4 * wy + a5 * wz;
            float m2v= a0 * wy + a6 * wz - a4 * wx;
            float m3 = a0 * wz - a5 * wx - a6 * wy;
            float m4 = a1 * wy + a7 * wz - a2 * wx;
            float m5 = a1 * wz - a3 * wx - a7 * wy;
            float m6 = a7 * wx - a3 * wy + a2 * wz;
            float m7 = a6 * wx - a5 * wy + a4 * wz;

            float* p = g_agg + (size_t)sdst * 128 + hlane * 8;
            asm volatile("red.global.add.v4.f32 [%0], {%1,%2,%3,%4};"
                         :: "l"(p), "f"(m0), "f"(m1), "f"(m2v), "f"(m3) : "memory");
            asm volatile("red.global.add.v4.f32 [%0], {%1,%2,%3,%4};"
                         :: "l"(p + 4), "f"(m4), "f"(m5), "f"(m6), "f"(m7) : "memory");
        }
    }
}

// ---------------- node pass: 32 nodes/block, 2 output channels/thread ----------------
// thread = (nl = t>>3, oo = t&7); computes output channels oo and oo+8.
// Warp spans 4 nodes -> 4 distinct LDS.128 addresses, 8-bank stagger => conflict-free.
#define NODE_STRIDE 136   // floats; 544B: 16B-aligned, +8 banks between nodes

__global__ void __launch_bounds__(256) node_kernel(
    const float* __restrict__ h,
    const float* __restrict__ Wout,   // [16,16] row-major W[c*16+o]
    const float* __restrict__ Wsgp,
    float* __restrict__ res,
    int N)
{
    __shared__ float s_a[32 * NODE_STRIDE];
    __shared__ float s_h[32 * NODE_STRIDE];
    __shared__ float s_wo[256];
    __shared__ float s_wq[256];

    int t = threadIdx.x;
    s_wo[t] = Wout[t];
    s_wq[t] = Wsgp[t];

    int basen = blockIdx.x * 32;
    int nv4 = min(32, N - basen) * 32;   // float4s per array

    const float4* ga = (const float4*)(g_agg + (size_t)basen * 128);
    const float4* gh = (const float4*)(h     + (size_t)basen * 128);
    #pragma unroll
    for (int k = 0; k < 4; k++) {
        int idx = t + k * 256;
        if (idx < nv4) {
            int node  = idx >> 5;
            int inner = idx & 31;
            float4 va = __ldg(ga + idx);
            float4 vh = __ldg(gh + idx);
            *(float4*)&s_a[node * NODE_STRIDE + inner * 4] = va;
            *(float4*)&s_h[node * NODE_STRIDE + inner * 4] = vh;
        }
    }
    __syncthreads();

    int nl = t >> 3;
    int node = basen + nl;
    if (node >= N) return;
    int oo = t & 7;                      // outputs oo and oo+8

    unsigned long long aA[4], aB[4], qA[4], qB[4];
    unsigned long long z = pack2(0.f, 0.f);
    #pragma unroll
    for (int i = 0; i < 4; i++) { aA[i] = z; aB[i] = z; qA[i] = z; qB[i] = z; }

    const float* A = s_a + nl * NODE_STRIDE;
    const float* H = s_h + nl * NODE_STRIDE;

    #pragma unroll
    for (int c = 0; c < 16; c++) {
        float woa = s_wo[c * 16 + oo];
        float wob = s_wo[c * 16 + oo + 8];
        float wqa = s_wq[c * 16 + oo];
        float wqb = s_wq[c * 16 + oo + 8];
        unsigned long long woa2 = pack2(woa, woa);
        unsigned long long wob2 = pack2(wob, wob);
        unsigned long long wqa2 = pack2(wqa, wqa);
        unsigned long long wqb2 = pack2(wqb, wqb);
        const float4* x = (const float4*)(A + c * 8);
        const float4* y = (const float4*)(H + c * 8);
        float4 x0 = x[0], x1 = x[1];
        float4 y0 = y[0], y1 = y[1];
        unsigned long long p0 = pack2(x0.x, x0.y), p1 = pack2(x0.z, x0.w);
        unsigned long long p2 = pack2(x1.x, x1.y), p3 = pack2(x1.z, x1.w);
        unsigned long long r0 = pack2(y0.x, y0.y), r1 = pack2(y0.z, y0.w);
        unsigned long long r2 = pack2(y1.x, y1.y), r3 = pack2(y1.z, y1.w);
        fma2(aA[0], p0, woa2); fma2(aA[1], p1, woa2);
        fma2(aA[2], p2, woa2); fma2(aA[3], p3, woa2);
        fma2(aB[0], p0, wob2); fma2(aB[1], p1, wob2);
        fma2(aB[2], p2, wob2); fma2(aB[3], p3, wob2);
        fma2(qA[0], r0, wqa2); fma2(qA[1], r1, wqa2);
        fma2(qA[2], r2, wqa2); fma2(qA[3], r3, wqa2);
        fma2(qB[0], r0, wqb2); fma2(qB[1], r1, wqb2);
        fma2(qB[2], r2, wqb2); fma2(qB[3], r3, wqb2);
    }

    float* outbase = res + (size_t)node * 128;

    #pragma unroll
    for (int half = 0; half < 2; half++) {
        unsigned long long* a2 = half ? aB : aA;
        unsigned long long* q2 = half ? qB : qA;
        float a[8], q[8];
        #pragma unroll
        for (int i = 0; i < 4; i++) {
            unpack2(a2[i], a[2 * i], a[2 * i + 1]);
            unpack2(q2[i], q[2 * i], q[2 * i + 1]);
        }

        float g0 = a[0]*q[0] + a[1]*q[1] + a[2]*q[2] + a[3]*q[3] - a[4]*q[4] - a[5]*q[5] - a[6]*q[6] - a[7]*q[7];
        float g1 = a[0]*q[1] + a[1]*q[0] - a[2]*q[4] - a[3]*q[5] + a[4]*q[2] + a[5]*q[3] - a[6]*q[7] - a[7]*q[6];
        float g2 = a[0]*q[2] + a[1]*q[4] + a[2]*q[0] - a[3]*q[6] - a[4]*q[1] + a[5]*q[7] + a[6]*q[3] + a[7]*q[5];
        float g3 = a[0]*q[3] + a[1]*q[5] + a[2]*q[6] + a[3]*q[0] - a[4]*q[7] - a[5]*q[1] - a[6]*q[2] - a[7]*q[4];
        float g4 = a[0]*q[4] + a[1]*q[2] - a[2]*q[1] + a[3]*q[7] + a[4]*q[0] - a[5]*q[6] + a[6]*q[5] + a[7]*q[3];
        float g5 = a[0]*q[5] + a[1]*q[3] - a[2]*q[7] - a[3]*q[1] + a[4]*q[6] + a[5]*q[0] - a[6]*q[4] - a[7]*q[2];
        float g6 = a[0]*q[6] + a[1]*q[7] + a[2]*q[3] - a[3]*q[2] - a[4]*q[5] + a[5]*q[4] + a[6]*q[0] + a[7]*q[1];
        float g7 = a[0]*q[7] + a[1]*q[6] - a[2]*q[5] + a[3]*q[4] + a[4]*q[3] - a[5]*q[2] + a[6]*q[1] + a[7]*q[0];

        float* op = outbase + (oo + half * 8) * 8;
        ((float4*)op)[0] = make_float4(a[0] + g0, a[1] + g1, a[2] + g2, a[3] + g3);
        ((float4*)op)[1] = make_float4(a[4] + g4, a[5] + g5, a[6] + g6, a[7] + g7);
    }
}

// ---------------- launch ----------------
extern "C" void kernel_launch(void* const* d_in, const int* in_sizes, int n_in,
                              void* d_out, int out_size)
{
    const float* h    = (const float*)d_in[0];
    const float* pos  = (const float*)d_in[1];
    const int*   ei   = (const int*)  d_in[2];
    const float* Wrbf = (const float*)d_in[3];
    const float* Wout = (const float*)d_in[4];
    const float* Wsgp = (const float*)d_in[5];
    float* out = (float*)d_out;

    int N = in_sizes[0] / 128;
    int E = in_sizes[2] / 2;
    if (N > MAXN) N = MAXN;

    void* agg_ptr = nullptr;
    cudaGetSymbolAddress(&agg_ptr, g_agg);
    cudaMemsetAsync(agg_ptr, 0, (size_t)N * 128 * sizeof(float), 0);

    int blocks = (E + 255) / 256;
    edge_fused_kernel<<<blocks, 256>>>(h, pos, ei, Wrbf, E);
    node_kernel<<<(N + 31) / 32, 256>>>(h, Wout, Wsgp, out, N);
}

// round 9
// speedup vs baseline: 1.5015x; 1.0315x over previous
#include <cuda_runtime.h>
#include <math.h>

// ---------------- problem constants ----------------
#define NRBF     32
#define CUTOFF_F 5.0f
#define GAMMA_F  40.96f                 // (NRBF/CUTOFF)^2
#define STEP_F   (5.0f / 31.0f)
#define INVSTEP_F (31.0f / 5.0f)
#define PI_F     3.14159265358979323846f
#define MAXN     50000

// scratch accumulator [N,16,8]
__device__ float g_agg[(size_t)MAXN * 128];

// ---------------- f32x2 packed helpers (FFMA2 path, sm_100+) ----------------
__device__ __forceinline__ unsigned long long pack2(float lo, float hi) {
    unsigned long long r;
    asm("mov.b64 %0, {%1, %2};" : "=l"(r) : "f"(lo), "f"(hi));
    return r;
}
__device__ __forceinline__ void unpack2(unsigned long long v, float& lo, float& hi) {
    asm("mov.b64 {%0, %1}, %2;" : "=f"(lo), "=f"(hi) : "l"(v));
}
__device__ __forceinline__ void fma2(unsigned long long& d,
                                     unsigned long long a,
                                     unsigned long long b) {
    asm("fma.rn.f32x2 %0, %1, %2, %3;" : "=l"(d) : "l"(a), "l"(b), "l"(d));
}

// ---------------- fused filter + edge pass (unchanged) ----------------
__global__ void __launch_bounds__(256) edge_fused_kernel(
    const float* __restrict__ h,
    const float* __restrict__ pos,
    const int*   __restrict__ ei,
    const float* __restrict__ Wrbf,   // [32,16] row-major
    int E)
{
    __shared__ float sW[NRBF * 16];
    int t = threadIdx.x;
    sW[t]       = Wrbf[t];
    sW[t + 256] = Wrbf[t + 256];
    __syncthreads();

    const unsigned FULL = 0xFFFFFFFFu;
    int lane  = t & 31;
    int hlane = t & 15;
    unsigned gbase = (unsigned)(t & 16);
    unsigned gmask = 0xFFFFu << gbase;
    int half  = (t >> 4) & 1;

    int e = (blockIdx.x * 8 + (t >> 5)) * 32 + lane;
    bool valid = e < E;
    int src = 0, dst = 0;
    if (valid) { src = __ldg(ei + e); dst = __ldg(ei + E + e); }

    float rx = 0.f, ry = 0.f, rz = 0.f;
    if (valid) {
        rx = __ldg(pos + dst * 3 + 0) - __ldg(pos + src * 3 + 0);
        ry = __ldg(pos + dst * 3 + 1) - __ldg(pos + src * 3 + 1);
        rz = __ldg(pos + dst * 3 + 2) - __ldg(pos + src * 3 + 2);
    }
    float d = sqrtf(rx * rx + ry * ry + rz * rz + 1e-12f);
    bool live = valid && (d < CUTOFF_F);
    float inv = 1.0f / d;
    float ux = rx * inv, uy = ry * inv, uz = rz * inv;

    unsigned mask = __ballot_sync(FULL, live);

    while (mask) {
        int s0 = __ffs(mask) - 1;
        unsigned m2 = mask & (mask - 1);
        int s1 = m2 ? (__ffs(m2) - 1) : 32;
        mask = m2 ? (m2 & (m2 - 1)) : 0u;

        int sl = half ? s1 : s0;
        bool act = sl < 32;
        int srcl = sl & 31;

        int   ssrc = __shfl_sync(FULL, src, srcl);
        int   sdst = __shfl_sync(FULL, dst, srcl);
        float sux  = __shfl_sync(FULL, ux,  srcl);
        float suy  = __shfl_sync(FULL, uy,  srcl);
        float suz  = __shfl_sync(FULL, uz,  srcl);
        float sd   = __shfl_sync(FULL, d,   srcl);

        if (act) {
            const float4* hp = (const float4*)(h + (size_t)ssrc * 128 + hlane * 8);
            float4 A0 = __ldg(hp), A1 = __ldg(hp + 1);

            int k0 = __float2int_rn(sd * INVSTEP_F);
            k0 = min(max(k0, 0), 31);
            float r = 0.f;
            {
                int k = k0 + hlane - 4;
                if (hlane < 9 && k >= 0 && k <= 31) {
                    float dd = sd - (float)k * STEP_F;
                    r = __expf(-GAMMA_F * dd * dd);
                }
            }
            float w = 0.f;
            #pragma unroll
            for (int m = 0; m < 9; m++) {
                float rm = __shfl_sync(gmask, r, gbase + m, 32);
                int km = k0 + m - 4;
                int kc = min(max(km, 0), 31);
                w += rm * sW[kc * 16 + hlane];
            }
            w *= 0.5f * (__cosf((PI_F / CUTOFF_F) * sd) + 1.0f);

            float wx = w * sux, wy = w * suy, wz = w * suz;

            float a0 = A0.x, a1 = A0.y, a2 = A0.z, a3 = A0.w;
            float a4 = A1.x, a5 = A1.y, a6 = A1.z, a7 = A1.w;

            float m0 = a1 * wx + a2 * wy + a3 * wz;
            float m1 = a0 * wx + a4 * wy + a5 * wz;
            float m2v= a0 * wy + a6 * wz - a4 * wx;
            float m3 = a0 * wz - a5 * wx - a6 * wy;
            float m4 = a1 * wy + a7 * wz - a2 * wx;
            float m5 = a1 * wz - a3 * wx - a7 * wy;
            float m6 = a7 * wx - a3 * wy + a2 * wz;
            float m7 = a6 * wx - a5 * wy + a4 * wz;

            float* p = g_agg + (size_t)sdst * 128 + hlane * 8;
            asm volatile("red.global.add.v4.f32 [%0], {%1,%2,%3,%4};"
                         :: "l"(p), "f"(m0), "f"(m1), "f"(m2v), "f"(m3) : "memory");
            asm volatile("red.global.add.v4.f32 [%0], {%1,%2,%3,%4};"
                         :: "l"(p + 4), "f"(m4), "f"(m5), "f"(m6), "f"(m7) : "memory");
        }
    }
}

// ---------------- node pass: 32 nodes/block, 4 output channels/thread ----------------
// 128 threads: thread = (nl = t>>2, oo = t&3); outputs {oo, oo+4, oo+8, oo+12}.
// Weights pre-transposed into float4 smem so each c costs 2 LDS.128 instead of 8 LDS.32.
#define NODE_STRIDE 136   // floats; 544B: 16B-aligned, +8 banks between nodes

__global__ void __launch_bounds__(128, 4) node_kernel(
    const float* __restrict__ h,
    const float* __restrict__ Wout,   // [16,16] row-major W[c*16+o]
    const float* __restrict__ Wsgp,
    float* __restrict__ res,
    int N)
{
    __shared__ float s_a[32 * NODE_STRIDE];
    __shared__ float s_h[32 * NODE_STRIDE];
    __shared__ float4 s_wo4[64];   // [c][oo] -> (W[c][oo],W[c][oo+4],W[c][oo+8],W[c][oo+12])
    __shared__ float4 s_wq4[64];

    int t = threadIdx.x;
    if (t < 64) {
        int c = t >> 2, oo = t & 3;
        const float* wr = Wout + c * 16 + oo;
        const float* qr = Wsgp + c * 16 + oo;
        s_wo4[t] = make_float4(wr[0], wr[4], wr[8], wr[12]);
        s_wq4[t] = make_float4(qr[0], qr[4], qr[8], qr[12]);
    }

    int basen = blockIdx.x * 32;
    int nv4 = min(32, N - basen) * 32;   // float4s per array

    const float4* ga = (const float4*)(g_agg + (size_t)basen * 128);
    const float4* gh = (const float4*)(h     + (size_t)basen * 128);
    #pragma unroll
    for (int k = 0; k < 8; k++) {
        int idx = t + k * 128;
        if (idx < nv4) {
            int node  = idx >> 5;
            int inner = idx & 31;
            float4 va = __ldg(ga + idx);
            float4 vh = __ldg(gh + idx);
            *(float4*)&s_a[node * NODE_STRIDE + inner * 4] = va;
            *(float4*)&s_h[node * NODE_STRIDE + inner * 4] = vh;
        }
    }
    __syncthreads();

    int nl = t >> 2;
    int node = basen + nl;
    if (node >= N) return;
    int oo = t & 3;

    unsigned long long aacc[4][4], qacc[4][4];
    unsigned long long z = pack2(0.f, 0.f);
    #pragma unroll
    for (int j = 0; j < 4; j++)
        #pragma unroll
        for (int i = 0; i < 4; i++) { aacc[j][i] = z; qacc[j][i] = z; }

    const float* A = s_a + nl * NODE_STRIDE;
    const float* H = s_h + nl * NODE_STRIDE;

    #pragma unroll
    for (int c = 0; c < 16; c++) {
        float4 w_o = s_wo4[c * 4 + oo];
        float4 w_q = s_wq4[c * 4 + oo];
        const float4* x = (const float4*)(A + c * 8);
        const float4* y = (const float4*)(H + c * 8);
        float4 x0 = x[0], x1 = x[1];
        float4 y0 = y[0], y1 = y[1];
        unsigned long long p0 = pack2(x0.x, x0.y), p1 = pack2(x0.z, x0.w);
        unsigned long long p2 = pack2(x1.x, x1.y), p3 = pack2(x1.z, x1.w);
        unsigned long long r0 = pack2(y0.x, y0.y), r1 = pack2(y0.z, y0.w);
        unsigned long long r2 = pack2(y1.x, y1.y), r3 = pack2(y1.z, y1.w);

        float wos[4] = {w_o.x, w_o.y, w_o.z, w_o.w};
        float wqs[4] = {w_q.x, w_q.y, w_q.z, w_q.w};
        #pragma unroll
        for (int j = 0; j < 4; j++) {
            unsigned long long wo2 = pack2(wos[j], wos[j]);
            unsigned long long wq2 = pack2(wqs[j], wqs[j]);
            fma2(aacc[j][0], p0, wo2); fma2(aacc[j][1], p1, wo2);
            fma2(aacc[j][2], p2, wo2); fma2(aacc[j][3], p3, wo2);
            fma2(qacc[j][0], r0, wq2); fma2(qacc[j][1], r1, wq2);
            fma2(qacc[j][2], r2, wq2); fma2(qacc[j][3], r3, wq2);
        }
    }

    float* outbase = res + (size_t)node * 128;

    #pragma unroll
    for (int j = 0; j < 4; j++) {
        float a[8], q[8];
        #pragma unroll
        for (int i = 0; i < 4; i++) {
            unpack2(aacc[j][i], a[2 * i], a[2 * i + 1]);
            unpack2(qacc[j][i], q[2 * i], q[2 * i + 1]);
        }

        float g0 = a[0]*q[0] + a[1]*q[1] + a[2]*q[2] + a[3]*q[3] - a[4]*q[4] - a[5]*q[5] - a[6]*q[6] - a[7]*q[7];
        float g1 = a[0]*q[1] + a[1]*q[0] - a[2]*q[4] - a[3]*q[5] + a[4]*q[2] + a[5]*q[3] - a[6]*q[7] - a[7]*q[6];
        float g2 = a[0]*q[2] + a[1]*q[4] + a[2]*q[0] - a[3]*q[6] - a[4]*q[1] + a[5]*q[7] + a[6]*q[3] + a[7]*q[5];
        float g3 = a[0]*q[3] + a[1]*q[5] + a[2]*q[6] + a[3]*q[0] - a[4]*q[7] - a[5]*q[1] - a[6]*q[2] - a[7]*q[4];
        float g4 = a[0]*q[4] + a[1]*q[2] - a[2]*q[1] + a[3]*q[7] + a[4]*q[0] - a[5]*q[6] + a[6]*q[5] + a[7]*q[3];
        float g5 = a[0]*q[5] + a[1]*q[3] - a[2]*q[7] - a[3]*q[1] + a[4]*q[6] + a[5]*q[0] - a[6]*q[4] - a[7]*q[2];
        float g6 = a[0]*q[6] + a[1]*q[7] + a[2]*q[3] - a[3]*q[2] - a[4]*q[5] + a[5]*q[4] + a[6]*q[0] + a[7]*q[1];
        float g7 = a[0]*q[7] + a[1]*q[6] - a[2]*q[5] + a[3]*q[4] + a[4]*q[3] - a[5]*q[2] + a[6]*q[1] + a[7]*q[0];

        float* op = outbase + (oo + j * 4) * 8;
        ((float4*)op)[0] = make_float4(a[0] + g0, a[1] + g1, a[2] + g2, a[3] + g3);
        ((float4*)op)[1] = make_float4(a[4] + g4, a[5] + g5, a[6] + g6, a[7] + g7);
    }
}

// ---------------- launch ----------------
extern "C" void kernel_launch(void* const* d_in, const int* in_sizes, int n_in,
                              void* d_out, int out_size)
{
    const float* h    = (const float*)d_in[0];
    const float* pos  = (const float*)d_in[1];
    const int*   ei   = (const int*)  d_in[2];
    const float* Wrbf = (const float*)d_in[3];
    const float* Wout = (const float*)d_in[4];
    const float* Wsgp = (const float*)d_in[5];
    float* out = (float*)d_out;

    int N = in_sizes[0] / 128;
    int E = in_sizes[2] / 2;
    if (N > MAXN) N = MAXN;

    void* agg_ptr = nullptr;
    cudaGetSymbolAddress(&agg_ptr, g_agg);
    cudaMemsetAsync(agg_ptr, 0, (size_t)N * 128 * sizeof(float), 0);

    int blocks = (E + 255) / 256;
    edge_fused_kernel<<<blocks, 256>>>(h, pos, ei, Wrbf, E);
    node_kernel<<<(N + 31) / 32, 128>>>(h, Wout, Wsgp, out, N);
}